// round 1
// baseline (speedup 1.0000x reference)
#include <cuda_runtime.h>

// HierarchyInvertClassifier: out[b,k,h,w] = bias[k] + sum_{c in group k} w[c]*in[b,c,h,w]
// B=8, C=64, H=W=512, K=12. Groups are contiguous channel ranges (static).
//
// Pure HBM-bound: 512 MiB read + 96 MiB write. float4-vectorized streaming kernel.

#define HW   (512 * 512)
#define HW4  (HW / 4)         // 65536
#define CCH  64
#define KOUT 12

__constant__ int kGroupStart[KOUT + 1] = {0, 1, 4, 14, 20, 28, 38, 46, 52, 57, 59, 62, 64};

__global__ __launch_bounds__(256)
void hier_invert_kernel(const float4* __restrict__ in4,
                        const float*  __restrict__ w,
                        const float*  __restrict__ bias,
                        float4* __restrict__ out4)
{
    __shared__ float sw[CCH];
    __shared__ float sb[KOUT];
    int t = threadIdx.x;
    if (t < CCH)  sw[t] = w[t];
    if (t < KOUT) sb[t] = bias[t];
    __syncthreads();

    int idx  = blockIdx.x * blockDim.x + t;   // 0 .. 8*65536-1
    int bimg = idx >> 16;                     // image index (0..7)
    int pvec = idx & 0xFFFF;                  // float4 position within plane

    const float4* ip = in4 + ((long)bimg * CCH) * HW4 + pvec;

    float4 acc[KOUT];
    #pragma unroll
    for (int k = 0; k < KOUT; k++) {
        float bk = sb[k];
        acc[k] = make_float4(bk, bk, bk, bk);
    }

    // Fully unrolled: 64 LDG.128 front-batched for max MLP, then FMAs.
    #pragma unroll
    for (int k = 0; k < KOUT; k++) {
        #pragma unroll
        for (int c = kGroupStart[k]; c < kGroupStart[k + 1]; c++) {
            float4 v = ip[(long)c * HW4];
            float  wc = sw[c];
            acc[k].x = fmaf(wc, v.x, acc[k].x);
            acc[k].y = fmaf(wc, v.y, acc[k].y);
            acc[k].z = fmaf(wc, v.z, acc[k].z);
            acc[k].w = fmaf(wc, v.w, acc[k].w);
        }
    }

    float4* op = out4 + ((long)bimg * KOUT) * HW4 + pvec;
    #pragma unroll
    for (int k = 0; k < KOUT; k++)
        op[(long)k * HW4] = acc[k];
}

extern "C" void kernel_launch(void* const* d_in, const int* in_sizes, int n_in,
                              void* d_out, int out_size)
{
    const float* pred_lr = (const float*)d_in[0];   // [8,64,512,512]
    const float* weights = (const float*)d_in[1];   // [64]
    const float* biases  = (const float*)d_in[2];   // [12]
    float* out = (float*)d_out;                     // [8,12,512,512]

    int total_vec = 8 * HW4;                        // 524288
    int threads = 256;
    int blocks  = total_vec / threads;              // 2048

    hier_invert_kernel<<<blocks, threads>>>(
        (const float4*)pred_lr, weights, biases, (float4*)out);
}

// round 2
// speedup vs baseline: 1.0999x; 1.0999x over previous
#include <cuda_runtime.h>

// HierarchyInvertClassifier: out[b,k,h,w] = bias[k] + sum_{c in group k} w[c]*in[b,c,h,w]
// B=8, C=64, H=W=512, K=12. Groups are contiguous channel ranges (static).
//
// HBM-bound: 512 MiB read + 96 MiB write. R2: per-group accumulate+store to
// cut register liveness (was 80 regs / occ 34%), reg-capped to 4 blocks/SM,
// streaming cache hints (zero reuse).

#define HW   (512 * 512)
#define HW4  (HW / 4)         // 65536
#define CCH  64
#define KOUT 12

__constant__ int kGroupStart[KOUT + 1] = {0, 1, 4, 14, 20, 28, 38, 46, 52, 57, 59, 62, 64};

__global__ __launch_bounds__(256, 4)
void hier_invert_kernel(const float4* __restrict__ in4,
                        const float*  __restrict__ w,
                        const float*  __restrict__ bias,
                        float4* __restrict__ out4)
{
    __shared__ float sw[CCH];
    __shared__ float sb[KOUT];
    int t = threadIdx.x;
    if (t < CCH)  sw[t] = w[t];
    if (t < KOUT) sb[t] = bias[t];
    __syncthreads();

    int idx  = blockIdx.x * blockDim.x + t;   // 0 .. 8*65536-1
    int bimg = idx >> 16;                     // image index (0..7)
    int pvec = idx & 0xFFFF;                  // float4 position within plane

    const float4* ip = in4 + ((long)bimg * CCH) * HW4 + pvec;
    float4*       op = out4 + ((long)bimg * KOUT) * HW4 + pvec;

    // Per-group: load group's channels (streaming), accumulate one float4,
    // store immediately. Keeps live regs ~ (group size * 4 + few), letting
    // ptxas batch loads within a group for MLP while occupancy doubles.
    #pragma unroll
    for (int k = 0; k < KOUT; k++) {
        const int c0 = kGroupStart[k];
        const int c1 = kGroupStart[k + 1];
        float bk = sb[k];
        float4 acc = make_float4(bk, bk, bk, bk);
        #pragma unroll
        for (int c = c0; c < c1; c++) {
            float4 v  = __ldcs(ip + (long)c * HW4);
            float  wc = sw[c];
            acc.x = fmaf(wc, v.x, acc.x);
            acc.y = fmaf(wc, v.y, acc.y);
            acc.z = fmaf(wc, v.z, acc.z);
            acc.w = fmaf(wc, v.w, acc.w);
        }
        __stcs(op + (long)k * HW4, acc);
    }
}

extern "C" void kernel_launch(void* const* d_in, const int* in_sizes, int n_in,
                              void* d_out, int out_size)
{
    const float* pred_lr = (const float*)d_in[0];   // [8,64,512,512]
    const float* weights = (const float*)d_in[1];   // [64]
    const float* biases  = (const float*)d_in[2];   // [12]
    float* out = (float*)d_out;                     // [8,12,512,512]

    int total_vec = 8 * HW4;                        // 524288
    int threads = 256;
    int blocks  = total_vec / threads;              // 2048

    hier_invert_kernel<<<blocks, threads>>>(
        (const float4*)pred_lr, weights, biases, (float4*)out);
}

// round 3
// speedup vs baseline: 1.1076x; 1.0070x over previous
#include <cuda_runtime.h>

// HierarchyInvertClassifier: out[b,k,h,w] = bias[k] + sum_{c in group k} w[c]*in[b,c,h,w]
// B=8, C=64, H=W=512, K=12. Groups are contiguous channel ranges (static).
//
// HBM-bound pure stream: 512 MiB read + 96 MiB write, zero reuse.
// R3: cap regs to 48 (5 blocks/SM = 40 warps) to raise SM-wide outstanding
// loads; per-group accumulate+store keeps liveness low; streaming hints.

#define HW   (512 * 512)
#define HW4  (HW / 4)         // 65536
#define CCH  64
#define KOUT 12

__constant__ int kGroupStart[KOUT + 1] = {0, 1, 4, 14, 20, 28, 38, 46, 52, 57, 59, 62, 64};

__global__ __launch_bounds__(256, 5)
void hier_invert_kernel(const float4* __restrict__ in4,
                        const float*  __restrict__ w,
                        const float*  __restrict__ bias,
                        float4* __restrict__ out4)
{
    __shared__ float sw[CCH];
    __shared__ float sb[KOUT];
    int t = threadIdx.x;
    if (t < CCH)  sw[t] = w[t];
    if (t < KOUT) sb[t] = bias[t];
    __syncthreads();

    int idx  = blockIdx.x * blockDim.x + t;   // 0 .. 8*65536-1
    int bimg = idx >> 16;                     // image index (0..7)
    int pvec = idx & 0xFFFF;                  // float4 position within plane

    const float4* ip = in4 + ((long)bimg * CCH) * HW4 + pvec;
    float4*       op = out4 + ((long)bimg * KOUT) * HW4 + pvec;

    #pragma unroll
    for (int k = 0; k < KOUT; k++) {
        const int c0 = kGroupStart[k];
        const int c1 = kGroupStart[k + 1];
        float bk = sb[k];
        float4 acc = make_float4(bk, bk, bk, bk);
        #pragma unroll
        for (int c = c0; c < c1; c++) {
            float4 v  = __ldcs(ip + (long)c * HW4);
            float  wc = sw[c];
            acc.x = fmaf(wc, v.x, acc.x);
            acc.y = fmaf(wc, v.y, acc.y);
            acc.z = fmaf(wc, v.z, acc.z);
            acc.w = fmaf(wc, v.w, acc.w);
        }
        __stcs(op + (long)k * HW4, acc);
    }
}

extern "C" void kernel_launch(void* const* d_in, const int* in_sizes, int n_in,
                              void* d_out, int out_size)
{
    const float* pred_lr = (const float*)d_in[0];   // [8,64,512,512]
    const float* weights = (const float*)d_in[1];   // [64]
    const float* biases  = (const float*)d_in[2];   // [12]
    float* out = (float*)d_out;                     // [8,12,512,512]

    int total_vec = 8 * HW4;                        // 524288
    int threads = 256;
    int blocks  = total_vec / threads;              // 2048

    hier_invert_kernel<<<blocks, threads>>>(
        (const float4*)pred_lr, weights, biases, (float4*)out);
}

// round 4
// speedup vs baseline: 1.1547x; 1.0425x over previous
#include <cuda_runtime.h>

// HierarchyInvertClassifier: out[b,k,h,w] = bias[k] + sum_{c in group k} w[c]*in[b,c,h,w]
// B=8, C=64, H=W=512, K=12. Groups are contiguous channel ranges (static).
//
// HBM-bound pure stream: 512 MiB read + 96 MiB write, zero reuse.
// R4: finer scheduling granularity — 128-thread blocks (4096 blocks,
// 10 blocks/SM, same 40 warps/SM) to halve the drain-tail quantum and
// smooth cross-CTA spread. Per-group accumulate+store, streaming hints.

#define HW   (512 * 512)
#define HW4  (HW / 4)         // 65536
#define CCH  64
#define KOUT 12

__constant__ int kGroupStart[KOUT + 1] = {0, 1, 4, 14, 20, 28, 38, 46, 52, 57, 59, 62, 64};

__global__ __launch_bounds__(128, 10)
void hier_invert_kernel(const float4* __restrict__ in4,
                        const float*  __restrict__ w,
                        const float*  __restrict__ bias,
                        float4* __restrict__ out4)
{
    __shared__ float sw[CCH];
    __shared__ float sb[KOUT];
    int t = threadIdx.x;
    if (t < CCH)  sw[t] = w[t];
    if (t < KOUT) sb[t] = bias[t];
    __syncthreads();

    int idx  = blockIdx.x * blockDim.x + t;   // 0 .. 8*65536-1
    int bimg = idx >> 16;                     // image index (0..7)
    int pvec = idx & 0xFFFF;                  // float4 position within plane

    const float4* ip = in4 + ((long)bimg * CCH) * HW4 + pvec;
    float4*       op = out4 + ((long)bimg * KOUT) * HW4 + pvec;

    #pragma unroll
    for (int k = 0; k < KOUT; k++) {
        const int c0 = kGroupStart[k];
        const int c1 = kGroupStart[k + 1];
        float bk = sb[k];
        float4 acc = make_float4(bk, bk, bk, bk);
        #pragma unroll
        for (int c = c0; c < c1; c++) {
            float4 v  = __ldcs(ip + (long)c * HW4);
            float  wc = sw[c];
            acc.x = fmaf(wc, v.x, acc.x);
            acc.y = fmaf(wc, v.y, acc.y);
            acc.z = fmaf(wc, v.z, acc.z);
            acc.w = fmaf(wc, v.w, acc.w);
        }
        __stcs(op + (long)k * HW4, acc);
    }
}

extern "C" void kernel_launch(void* const* d_in, const int* in_sizes, int n_in,
                              void* d_out, int out_size)
{
    const float* pred_lr = (const float*)d_in[0];   // [8,64,512,512]
    const float* weights = (const float*)d_in[1];   // [64]
    const float* biases  = (const float*)d_in[2];   // [12]
    float* out = (float*)d_out;                     // [8,12,512,512]

    int total_vec = 8 * HW4;                        // 524288
    int threads = 128;
    int blocks  = total_vec / threads;              // 4096

    hier_invert_kernel<<<blocks, threads>>>(
        (const float4*)pred_lr, weights, biases, (float4*)out);
}